// round 8
// baseline (speedup 1.0000x reference)
#include <cuda_runtime.h>

#define NN 50000
#define NE 800000
#define CIN 128
#define CH 64
#define NB 196       // ceil(NN/256)
#define GB_DEG 782   // ceil(NE/1024): deg blocks, 4 edges/thread
#define GB_GEMM 782  // ceil(NN/64): gemm1 tiles
#define GB_RE 782    // ceil(NE/1024): reorder blocks, 4 edges/thread

// ---------------- scratch (no allocs allowed -> device globals) ----------------
__device__ int   g_cnt[NN];        // in-degree histogram; self-cleaned by k_off
__device__ int   g_off[NN];        // CSR segment start per node
__device__ int   g_end[NN];        // CSR segment end per node
__device__ int   g_cur[NN];        // reorder cursors
__device__ float g_dis[NN];        // rsqrt(deg+1)
__device__ int   g_eidx[NE];       // dst-grouped src indices (CSR adjacency)
__device__ int   g_total;          // atomic base counter (reset by fused kernel)
__device__ float g_h1[(size_t)NN * CH];   // RAW x @ W1 (dis applied in gather1)
__device__ float g_acc1[(size_t)NN * CH]; // layer-1 output (post-bias, pre-ReLU)
__device__ float g_h2[(size_t)NN * CH];   // dis[i] * (relu(acc1) @ W2)

// ---------------- packed f32x2 helpers ----------------
__device__ __forceinline__ unsigned long long pack_dup(float v) {
    unsigned long long r;
    asm("mov.b64 %0, {%1, %1};" : "=l"(r) : "r"(__float_as_uint(v)));
    return r;
}
__device__ __forceinline__ void ffma2(unsigned long long& d, unsigned long long a,
                                      unsigned long long b) {
    asm("fma.rn.f32x2 %0, %1, %2, %3;" : "=l"(d) : "l"(a), "l"(b), "l"(d));
}
__device__ __forceinline__ unsigned long long fmul2(unsigned long long a,
                                                    unsigned long long b) {
    unsigned long long r;
    asm("mul.rn.f32x2 %0, %1, %2;" : "=l"(r) : "l"(a), "l"(b));
    return r;
}

// per-block int64-vs-int32 detection (reads 16 leading entries; L2-hot)
__device__ __forceinline__ int detect64(const void* idx) {
    const long long* p = (const long long*)idx;
    int ok = 1;
    for (int j = 0; j < 16; j++) {
        long long v = p[j];
        if (v < 0 || v >= NN) ok = 0;
    }
    return ok;
}

// ---------------- fused: degree histogram (blocks 0..GB_DEG) || GEMM1 ----------------
// deg: 4 edges/thread, vectorized index loads, atomic histogram. gemm1: 64x64
// tile, 256 threads, 2x8 thread tile, f32x2 FMA; writes RAW x@W1 (no dis).
__global__ __launch_bounds__(256) void k_fused1(const float* __restrict__ x,
                                                const float* __restrict__ W,
                                                const void* __restrict__ idx) {
    if (blockIdx.x < GB_DEG) {
        __shared__ int s64;
        const int t = threadIdx.x;
        if (t == 0) {
            s64 = detect64(idx);
            if (blockIdx.x == 0) g_total = 0;  // reset base counter for k_off
        }
        __syncthreads();
        int e0 = (blockIdx.x * 256 + t) * 4;
        if (e0 < NE) {  // NE%4==0 so e0<NE implies e0+3<NE
            int d0, d1, d2, d3;
            if (s64) {
                const ulonglong2* pd =
                    (const ulonglong2*)((const long long*)idx + NE + e0);
                ulonglong2 a = __ldg(pd), b = __ldg(pd + 1);
                d0 = (int)a.x; d1 = (int)a.y; d2 = (int)b.x; d3 = (int)b.y;
            } else {
                int4 dv = __ldg((const int4*)((const int*)idx + NE + e0));
                d0 = dv.x; d1 = dv.y; d2 = dv.z; d3 = dv.w;
            }
            atomicAdd(&g_cnt[d0], 1);
            atomicAdd(&g_cnt[d1], 1);
            atomicAdd(&g_cnt[d2], 1);
            atomicAdd(&g_cnt[d3], 1);
        }
        return;
    }

    // ---- GEMM1 part ----
    extern __shared__ float sm[];
    float* Ws = sm;             // 128*64
    float* Xs = sm + CIN * CH;  // 64*130
    const int t = threadIdx.x;
    const int row0 = (blockIdx.x - GB_DEG) * 64;

    {
        const float4* Wg = (const float4*)W;
        float4* Wsv = (float4*)Ws;
        #pragma unroll
        for (int i = 0; i < 8; i++) Wsv[i * 256 + t] = Wg[i * 256 + t];
    }
    #pragma unroll
    for (int i = 0; i < 32; i++) {
        int e = i * 256 + t;
        int r = e >> 7, c = e & 127;
        int gr = row0 + r;
        Xs[r * 130 + c] = (gr < NN) ? __ldg(x + (size_t)gr * CIN + c) : 0.0f;
    }
    __syncthreads();

    const int tx = t & 7;   // 8 col groups of 8
    const int ty = t >> 3;  // 32 row groups of 2
    const float* Xp = Xs + ty * 2 * 130;
    const float* Wp = Ws + tx * 8;
    unsigned long long acc[2][4];
    #pragma unroll
    for (int r = 0; r < 2; r++)
        #pragma unroll
        for (int p = 0; p < 4; p++) acc[r][p] = 0ull;

    #pragma unroll 4
    for (int k = 0; k < CIN; k++) {
        ulonglong2 w01 = *(const ulonglong2*)(Wp + k * CH);
        ulonglong2 w23 = *(const ulonglong2*)(Wp + k * CH + 4);
        #pragma unroll
        for (int r = 0; r < 2; r++) {
            unsigned long long xx = pack_dup(Xp[r * 130 + k]);
            ffma2(acc[r][0], xx, w01.x);
            ffma2(acc[r][1], xx, w01.y);
            ffma2(acc[r][2], xx, w23.x);
            ffma2(acc[r][3], xx, w23.y);
        }
    }

    #pragma unroll
    for (int r = 0; r < 2; r++) {
        int gr = row0 + ty * 2 + r;
        if (gr < NN) {
            float* hp = g_h1 + (size_t)gr * CH + tx * 8;
            *(ulonglong2*)hp = make_ulonglong2(acc[r][0], acc[r][1]);
            *(ulonglong2*)(hp + 4) = make_ulonglong2(acc[r][2], acc[r][3]);
        }
    }
}

// ---------------- fused offsets: block scan + atomic block base ----------------
__global__ __launch_bounds__(256) void k_off() {
    __shared__ int sm[256];
    __shared__ int sbase;
    const int t = threadIdx.x;
    int i = blockIdx.x * 256 + t;
    int c = (i < NN) ? g_cnt[i] : 0;
    sm[t] = c;
    __syncthreads();
    for (int o = 1; o < 256; o <<= 1) {
        int u = (t >= o) ? sm[t - o] : 0;
        __syncthreads();
        sm[t] += u;
        __syncthreads();
    }
    if (t == 255) sbase = atomicAdd(&g_total, sm[255]);
    __syncthreads();
    int off = sbase + sm[t] - c;
    if (i < NN) {
        g_off[i] = off;
        g_end[i] = off + c;
        g_cur[i] = off;
        g_dis[i] = rsqrtf((float)(c + 1));  // degree includes self-loop
        g_cnt[i] = 0;                       // clean for next call
    }
}

// ---------------- reorder: 4 edges/thread, reads edge_index directly ----------------
__global__ __launch_bounds__(256) void k_reorder(const void* __restrict__ idx) {
    __shared__ int s64;
    const int t = threadIdx.x;
    if (t == 0) s64 = detect64(idx);
    __syncthreads();
    int e0 = (blockIdx.x * 256 + t) * 4;
    if (e0 >= NE) return;
    int s0, s1, s2, s3, d0, d1, d2, d3;
    if (s64) {
        const long long* p = (const long long*)idx;
        ulonglong2 a = __ldg((const ulonglong2*)(p + e0));
        ulonglong2 b = __ldg((const ulonglong2*)(p + e0) + 1);
        ulonglong2 c = __ldg((const ulonglong2*)(p + NE + e0));
        ulonglong2 d = __ldg((const ulonglong2*)(p + NE + e0) + 1);
        s0 = (int)a.x; s1 = (int)a.y; s2 = (int)b.x; s3 = (int)b.y;
        d0 = (int)c.x; d1 = (int)c.y; d2 = (int)d.x; d3 = (int)d.y;
    } else {
        const int* p = (const int*)idx;
        int4 a = __ldg((const int4*)(p + e0));
        int4 c = __ldg((const int4*)(p + NE + e0));
        s0 = a.x; s1 = a.y; s2 = a.z; s3 = a.w;
        d0 = c.x; d1 = c.y; d2 = c.z; d3 = c.w;
    }
    int p0 = atomicAdd(&g_cur[d0], 1);
    int p1 = atomicAdd(&g_cur[d1], 1);
    int p2 = atomicAdd(&g_cur[d2], 1);
    int p3 = atomicAdd(&g_cur[d3], 1);
    g_eidx[p0] = s0;
    g_eidx[p1] = s1;
    g_eidx[p2] = s2;
    g_eidx[p3] = s3;
}

// ---------------- GEMM2: h2 = dis[row] * (relu(acc1) @ W2), f32x2 ----------------
__global__ __launch_bounds__(128) void k_gemm2(const float* __restrict__ W) {
    __shared__ float Ws[CH * CH];
    __shared__ float Xs[64 * 66];
    const int t = threadIdx.x;
    const int row0 = blockIdx.x * 64;

    {
        const float4* Wg = (const float4*)W;
        float4* Wsv = (float4*)Ws;
        #pragma unroll
        for (int i = 0; i < 8; i++) Wsv[i * 128 + t] = Wg[i * 128 + t];
    }
    #pragma unroll
    for (int i = 0; i < 32; i++) {
        int e = i * 128 + t;
        int r = e >> 6, c = e & 63;
        int gr = row0 + r;
        float v = (gr < NN) ? g_acc1[(size_t)gr * CH + c] : 0.0f;
        Xs[r * 66 + c] = fmaxf(v, 0.0f);  // fused ReLU
    }
    __syncthreads();

    const int tx = t & 7;
    const int ty = t >> 3;
    const float* Xp = Xs + ty * 4 * 66;
    const float* Wp = Ws + tx * 8;
    unsigned long long acc[4][4];
    #pragma unroll
    for (int r = 0; r < 4; r++)
        #pragma unroll
        for (int p = 0; p < 4; p++) acc[r][p] = 0ull;

    #pragma unroll 4
    for (int k = 0; k < CH; k++) {
        ulonglong2 w01 = *(const ulonglong2*)(Wp + k * CH);
        ulonglong2 w23 = *(const ulonglong2*)(Wp + k * CH + 4);
        #pragma unroll
        for (int r = 0; r < 4; r++) {
            unsigned long long xx = pack_dup(Xp[r * 66 + k]);
            ffma2(acc[r][0], xx, w01.x);
            ffma2(acc[r][1], xx, w01.y);
            ffma2(acc[r][2], xx, w23.x);
            ffma2(acc[r][3], xx, w23.y);
        }
    }

    #pragma unroll
    for (int r = 0; r < 4; r++) {
        int gr = row0 + ty * 4 + r;
        if (gr < NN) {
            unsigned long long dd = pack_dup(g_dis[gr]);
            float* hp = g_h2 + (size_t)gr * CH + tx * 8;
            *(ulonglong2*)hp = make_ulonglong2(fmul2(acc[r][0], dd), fmul2(acc[r][1], dd));
            *(ulonglong2*)(hp + 4) = make_ulonglong2(fmul2(acc[r][2], dd), fmul2(acc[r][3], dd));
        }
    }
}

// ---------------- CSR gather ----------------
// L==1: h1 is RAW -> per-edge fmaf(dis[sj], v, acc), self term dis[i]*h[i].
// L==2: h2 already dis-scaled -> pure sums.
// One warp per node, lane owns 2 columns, 4x unrolled for MLP.
template <int L>
__global__ __launch_bounds__(256) void k_gather(const float* __restrict__ b,
                                                float* __restrict__ out_arg) {
    const int node = blockIdx.x * 8 + (threadIdx.x >> 5);
    const int lane = threadIdx.x & 31;
    if (node >= NN) return;
    const float* __restrict__ hs = (L == 1) ? g_h1 : g_h2;
    float* __restrict__ dst = (L == 1) ? g_acc1 : out_arg;

    const float dsi = g_dis[node];
    float2 hv = __ldg((const float2*)(hs + (size_t)node * CH) + lane);
    float2 acc;
    if (L == 1) {
        acc.x = dsi * hv.x;
        acc.y = dsi * hv.y;
    } else {
        acc = hv;
    }

    int e = g_off[node];
    const int s1 = g_end[node];
    for (; e + 4 <= s1; e += 4) {
        int sj0 = __ldg(g_eidx + e);
        int sj1 = __ldg(g_eidx + e + 1);
        int sj2 = __ldg(g_eidx + e + 2);
        int sj3 = __ldg(g_eidx + e + 3);
        float2 v0 = __ldg((const float2*)(hs + (size_t)sj0 * CH) + lane);
        float2 v1 = __ldg((const float2*)(hs + (size_t)sj1 * CH) + lane);
        float2 v2 = __ldg((const float2*)(hs + (size_t)sj2 * CH) + lane);
        float2 v3 = __ldg((const float2*)(hs + (size_t)sj3 * CH) + lane);
        if (L == 1) {
            float e0 = __ldg(g_dis + sj0), e1 = __ldg(g_dis + sj1);
            float e2 = __ldg(g_dis + sj2), e3 = __ldg(g_dis + sj3);
            acc.x = fmaf(e0, v0.x, acc.x); acc.y = fmaf(e0, v0.y, acc.y);
            acc.x = fmaf(e1, v1.x, acc.x); acc.y = fmaf(e1, v1.y, acc.y);
            acc.x = fmaf(e2, v2.x, acc.x); acc.y = fmaf(e2, v2.y, acc.y);
            acc.x = fmaf(e3, v3.x, acc.x); acc.y = fmaf(e3, v3.y, acc.y);
        } else {
            acc.x += v0.x + v1.x + v2.x + v3.x;
            acc.y += v0.y + v1.y + v2.y + v3.y;
        }
    }
    for (; e < s1; e++) {
        int sj = __ldg(g_eidx + e);
        float2 v = __ldg((const float2*)(hs + (size_t)sj * CH) + lane);
        if (L == 1) {
            float ee = __ldg(g_dis + sj);
            acc.x = fmaf(ee, v.x, acc.x);
            acc.y = fmaf(ee, v.y, acc.y);
        } else {
            acc.x += v.x;
            acc.y += v.y;
        }
    }

    float2 bv = __ldg((const float2*)b + lane);
    float2 o;
    o.x = dsi * acc.x + bv.x;
    o.y = dsi * acc.y + bv.y;
    *((float2*)(dst + (size_t)node * CH) + lane) = o;
}

// ---------------- launch ----------------
extern "C" void kernel_launch(void* const* d_in, const int* in_sizes, int n_in,
                              void* d_out, int out_size) {
    const float* x  = (const float*)d_in[0];
    const void*  ei = d_in[1];
    const float* W1 = (const float*)d_in[2];
    const float* b1 = (const float*)d_in[3];
    const float* W2 = (const float*)d_in[4];
    const float* b2 = (const float*)d_in[5];
    float* out = (float*)d_out;

    const int smem1 = (CIN * CH + 64 * 130) * (int)sizeof(float);  // ~64.5 KB
    cudaFuncSetAttribute(k_fused1, cudaFuncAttributeMaxDynamicSharedMemorySize,
                         smem1);

    k_fused1<<<GB_DEG + GB_GEMM, 256, smem1>>>(x, W1, ei);  // deg || gemm1
    k_off<<<NB, 256>>>();
    k_reorder<<<GB_RE, 256>>>(ei);
    k_gather<1><<<(NN + 7) / 8, 256>>>(b1, nullptr);
    k_gemm2<<<(NN + 63) / 64, 128>>>(W2);
    k_gather<2><<<(NN + 7) / 8, 256>>>(b2, out);
}

// round 9
// speedup vs baseline: 1.1811x; 1.1811x over previous
#include <cuda_runtime.h>

#define NN 50000
#define NE 800000
#define CIN 128
#define CH 64
#define NB 196      // ceil(NN/256)
#define GB_E4 782   // ceil(NE/1024): edge kernels, 4 edges/thread

// ---------------- scratch (no allocs allowed -> device globals) ----------------
__device__ int   g_cnt[NN];        // in-degree histogram; self-cleaned by k_off
__device__ int   g_off[NN];        // CSR segment start per node
__device__ int   g_end[NN];        // CSR segment end per node
__device__ int   g_cur[NN];        // reorder cursors
__device__ float g_dis[NN];        // rsqrt(deg+1)
__device__ int   g_eidx[NE];       // dst-grouped src indices (CSR adjacency)
__device__ int   g_total;          // atomic base counter (reset by k_deg block 0)
__device__ float g_h1[(size_t)NN * CH];   // dis[i] * (x @ W1)
__device__ float g_acc1[(size_t)NN * CH]; // layer-1 output (post-bias, pre-ReLU)
__device__ float g_h2[(size_t)NN * CH];   // dis[i] * (relu(acc1) @ W2)

// ---------------- packed f32x2 helpers ----------------
__device__ __forceinline__ unsigned long long pack_dup(float v) {
    unsigned long long r;
    asm("mov.b64 %0, {%1, %1};" : "=l"(r) : "r"(__float_as_uint(v)));
    return r;
}
__device__ __forceinline__ void ffma2(unsigned long long& d, unsigned long long a,
                                      unsigned long long b) {
    asm("fma.rn.f32x2 %0, %1, %2, %3;" : "=l"(d) : "l"(a), "l"(b), "l"(d));
}
__device__ __forceinline__ unsigned long long fmul2(unsigned long long a,
                                                    unsigned long long b) {
    unsigned long long r;
    asm("mul.rn.f32x2 %0, %1, %2;" : "=l"(r) : "l"(a), "l"(b));
    return r;
}

// per-block int64-vs-int32 detection (reads 16 leading entries; L2-hot)
__device__ __forceinline__ int detect64(const void* idx) {
    const long long* p = (const long long*)idx;
    int ok = 1;
    for (int j = 0; j < 16; j++) {
        long long v = p[j];
        if (v < 0 || v >= NN) ok = 0;
    }
    return ok;
}

// ---------------- degree histogram: 4 edges/thread, vectorized ----------------
__global__ __launch_bounds__(256) void k_deg(const void* __restrict__ idx) {
    __shared__ int s64;
    const int t = threadIdx.x;
    if (t == 0) {
        s64 = detect64(idx);
        if (blockIdx.x == 0) g_total = 0;  // reset base counter for k_off
    }
    __syncthreads();
    int e0 = (blockIdx.x * 256 + t) * 4;
    if (e0 >= NE) return;  // NE%4==0 -> full quad
    int d0, d1, d2, d3;
    if (s64) {
        const ulonglong2* pd = (const ulonglong2*)((const long long*)idx + NE + e0);
        ulonglong2 a = __ldg(pd), b = __ldg(pd + 1);
        d0 = (int)a.x; d1 = (int)a.y; d2 = (int)b.x; d3 = (int)b.y;
    } else {
        int4 dv = __ldg((const int4*)((const int*)idx + NE + e0));
        d0 = dv.x; d1 = dv.y; d2 = dv.z; d3 = dv.w;
    }
    atomicAdd(&g_cnt[d0], 1);
    atomicAdd(&g_cnt[d1], 1);
    atomicAdd(&g_cnt[d2], 1);
    atomicAdd(&g_cnt[d3], 1);
}

// ---------------- fused offsets: block scan + atomic block base ----------------
__global__ __launch_bounds__(256) void k_off() {
    __shared__ int sm[256];
    __shared__ int sbase;
    const int t = threadIdx.x;
    int i = blockIdx.x * 256 + t;
    int c = (i < NN) ? g_cnt[i] : 0;
    sm[t] = c;
    __syncthreads();
    for (int o = 1; o < 256; o <<= 1) {
        int u = (t >= o) ? sm[t - o] : 0;
        __syncthreads();
        sm[t] += u;
        __syncthreads();
    }
    if (t == 255) sbase = atomicAdd(&g_total, sm[255]);
    __syncthreads();
    int off = sbase + sm[t] - c;
    if (i < NN) {
        g_off[i] = off;
        g_end[i] = off + c;
        g_cur[i] = off;
        g_dis[i] = rsqrtf((float)(c + 1));  // degree includes self-loop
        g_cnt[i] = 0;                       // clean for next call
    }
}

// ---------------- reorder: 4 edges/thread, reads edge_index directly ----------------
__global__ __launch_bounds__(256) void k_reorder(const void* __restrict__ idx) {
    __shared__ int s64;
    const int t = threadIdx.x;
    if (t == 0) s64 = detect64(idx);
    __syncthreads();
    int e0 = (blockIdx.x * 256 + t) * 4;
    if (e0 >= NE) return;
    int s0, s1, s2, s3, d0, d1, d2, d3;
    if (s64) {
        const long long* p = (const long long*)idx;
        ulonglong2 a = __ldg((const ulonglong2*)(p + e0));
        ulonglong2 b = __ldg((const ulonglong2*)(p + e0) + 1);
        ulonglong2 c = __ldg((const ulonglong2*)(p + NE + e0));
        ulonglong2 d = __ldg((const ulonglong2*)(p + NE + e0) + 1);
        s0 = (int)a.x; s1 = (int)a.y; s2 = (int)b.x; s3 = (int)b.y;
        d0 = (int)c.x; d1 = (int)c.y; d2 = (int)d.x; d3 = (int)d.y;
    } else {
        const int* p = (const int*)idx;
        int4 a = __ldg((const int4*)(p + e0));
        int4 c = __ldg((const int4*)(p + NE + e0));
        s0 = a.x; s1 = a.y; s2 = a.z; s3 = a.w;
        d0 = c.x; d1 = c.y; d2 = c.z; d3 = c.w;
    }
    int p0 = atomicAdd(&g_cur[d0], 1);
    int p1 = atomicAdd(&g_cur[d1], 1);
    int p2 = atomicAdd(&g_cur[d2], 1);
    int p3 = atomicAdd(&g_cur[d3], 1);
    g_eidx[p0] = s0;
    g_eidx[p1] = s1;
    g_eidx[p2] = s2;
    g_eidx[p3] = s3;
}

// ---------------- GEMM1: h1 = dis[row] * (x @ W1), f32x2, 128 thr, 4x8 tile ----------------
__global__ __launch_bounds__(128) void k_gemm1(const float* __restrict__ x,
                                               const float* __restrict__ W) {
    extern __shared__ float sm[];
    float* Ws = sm;             // 128*64
    float* Xs = sm + CIN * CH;  // 64*130
    const int t = threadIdx.x;
    const int row0 = blockIdx.x * 64;

    {
        const float4* Wg = (const float4*)W;
        float4* Wsv = (float4*)Ws;
        #pragma unroll
        for (int i = 0; i < 16; i++) Wsv[i * 128 + t] = Wg[i * 128 + t];
    }
    #pragma unroll
    for (int i = 0; i < 64; i++) {
        int e = i * 128 + t;
        int r = e >> 7, c = e & 127;
        int gr = row0 + r;
        Xs[r * 130 + c] = (gr < NN) ? __ldg(x + (size_t)gr * CIN + c) : 0.0f;
    }
    __syncthreads();

    const int tx = t & 7;
    const int ty = t >> 3;
    const float* Xp = Xs + ty * 4 * 130;
    const float* Wp = Ws + tx * 8;
    unsigned long long acc[4][4];
    #pragma unroll
    for (int r = 0; r < 4; r++)
        #pragma unroll
        for (int p = 0; p < 4; p++) acc[r][p] = 0ull;

    #pragma unroll 4
    for (int k = 0; k < CIN; k++) {
        ulonglong2 w01 = *(const ulonglong2*)(Wp + k * CH);
        ulonglong2 w23 = *(const ulonglong2*)(Wp + k * CH + 4);
        #pragma unroll
        for (int r = 0; r < 4; r++) {
            unsigned long long xx = pack_dup(Xp[r * 130 + k]);
            ffma2(acc[r][0], xx, w01.x);
            ffma2(acc[r][1], xx, w01.y);
            ffma2(acc[r][2], xx, w23.x);
            ffma2(acc[r][3], xx, w23.y);
        }
    }

    #pragma unroll
    for (int r = 0; r < 4; r++) {
        int gr = row0 + ty * 4 + r;
        if (gr < NN) {
            unsigned long long dd = pack_dup(g_dis[gr]);
            float* hp = g_h1 + (size_t)gr * CH + tx * 8;
            *(ulonglong2*)hp = make_ulonglong2(fmul2(acc[r][0], dd), fmul2(acc[r][1], dd));
            *(ulonglong2*)(hp + 4) = make_ulonglong2(fmul2(acc[r][2], dd), fmul2(acc[r][3], dd));
        }
    }
}

// ---------------- GEMM2: h2 = dis[row] * (relu(acc1) @ W2), f32x2 ----------------
__global__ __launch_bounds__(128) void k_gemm2(const float* __restrict__ W) {
    __shared__ float Ws[CH * CH];
    __shared__ float Xs[64 * 66];
    const int t = threadIdx.x;
    const int row0 = blockIdx.x * 64;

    {
        const float4* Wg = (const float4*)W;
        float4* Wsv = (float4*)Ws;
        #pragma unroll
        for (int i = 0; i < 8; i++) Wsv[i * 128 + t] = Wg[i * 128 + t];
    }
    #pragma unroll
    for (int i = 0; i < 32; i++) {
        int e = i * 128 + t;
        int r = e >> 6, c = e & 63;
        int gr = row0 + r;
        float v = (gr < NN) ? g_acc1[(size_t)gr * CH + c] : 0.0f;
        Xs[r * 66 + c] = fmaxf(v, 0.0f);  // fused ReLU
    }
    __syncthreads();

    const int tx = t & 7;
    const int ty = t >> 3;
    const float* Xp = Xs + ty * 4 * 66;
    const float* Wp = Ws + tx * 8;
    unsigned long long acc[4][4];
    #pragma unroll
    for (int r = 0; r < 4; r++)
        #pragma unroll
        for (int p = 0; p < 4; p++) acc[r][p] = 0ull;

    #pragma unroll 4
    for (int k = 0; k < CH; k++) {
        ulonglong2 w01 = *(const ulonglong2*)(Wp + k * CH);
        ulonglong2 w23 = *(const ulonglong2*)(Wp + k * CH + 4);
        #pragma unroll
        for (int r = 0; r < 4; r++) {
            unsigned long long xx = pack_dup(Xp[r * 66 + k]);
            ffma2(acc[r][0], xx, w01.x);
            ffma2(acc[r][1], xx, w01.y);
            ffma2(acc[r][2], xx, w23.x);
            ffma2(acc[r][3], xx, w23.y);
        }
    }

    #pragma unroll
    for (int r = 0; r < 4; r++) {
        int gr = row0 + ty * 4 + r;
        if (gr < NN) {
            unsigned long long dd = pack_dup(g_dis[gr]);
            float* hp = g_h2 + (size_t)gr * CH + tx * 8;
            *(ulonglong2*)hp = make_ulonglong2(fmul2(acc[r][0], dd), fmul2(acc[r][1], dd));
            *(ulonglong2*)(hp + 4) = make_ulonglong2(fmul2(acc[r][2], dd), fmul2(acc[r][3], dd));
        }
    }
}

// ---------------- CSR gather: dst[i] = dis[i]*(hs[i] + sum_e hs[src_e]) + b ----------------
// hs is pre-scaled by dis -> pure adds per edge (minimum instruction form;
// R8 showed per-edge dis loads cost ~3.5us). One warp/node, lane owns 2 cols,
// 4x unrolled for MLP. Destination chosen in device code (never pass a
// __device__ symbol as a host-side kernel arg).
template <int L>
__global__ __launch_bounds__(256) void k_gather(const float* __restrict__ b,
                                                float* __restrict__ out_arg) {
    const int node = blockIdx.x * 8 + (threadIdx.x >> 5);
    const int lane = threadIdx.x & 31;
    if (node >= NN) return;
    const float* __restrict__ hs = (L == 1) ? g_h1 : g_h2;
    float* __restrict__ dst = (L == 1) ? g_acc1 : out_arg;

    float2 acc = __ldg((const float2*)(hs + (size_t)node * CH) + lane);  // self term

    int e = g_off[node];
    const int s1 = g_end[node];
    for (; e + 4 <= s1; e += 4) {
        int sj0 = __ldg(g_eidx + e);
        int sj1 = __ldg(g_eidx + e + 1);
        int sj2 = __ldg(g_eidx + e + 2);
        int sj3 = __ldg(g_eidx + e + 3);
        float2 v0 = __ldg((const float2*)(hs + (size_t)sj0 * CH) + lane);
        float2 v1 = __ldg((const float2*)(hs + (size_t)sj1 * CH) + lane);
        float2 v2 = __ldg((const float2*)(hs + (size_t)sj2 * CH) + lane);
        float2 v3 = __ldg((const float2*)(hs + (size_t)sj3 * CH) + lane);
        acc.x += v0.x + v1.x + v2.x + v3.x;
        acc.y += v0.y + v1.y + v2.y + v3.y;
    }
    for (; e < s1; e++) {
        int sj = __ldg(g_eidx + e);
        float2 v = __ldg((const float2*)(hs + (size_t)sj * CH) + lane);
        acc.x += v.x;
        acc.y += v.y;
    }

    float ds = g_dis[node];
    float2 bv = __ldg((const float2*)b + lane);
    float2 o;
    o.x = ds * acc.x + bv.x;
    o.y = ds * acc.y + bv.y;
    *((float2*)(dst + (size_t)node * CH) + lane) = o;
}

// ---------------- launch ----------------
extern "C" void kernel_launch(void* const* d_in, const int* in_sizes, int n_in,
                              void* d_out, int out_size) {
    const float* x  = (const float*)d_in[0];
    const void*  ei = d_in[1];
    const float* W1 = (const float*)d_in[2];
    const float* b1 = (const float*)d_in[3];
    const float* W2 = (const float*)d_in[4];
    const float* b2 = (const float*)d_in[5];
    float* out = (float*)d_out;

    const int smem1 = (CIN * CH + 64 * 130) * (int)sizeof(float);  // ~64.5 KB
    cudaFuncSetAttribute(k_gemm1, cudaFuncAttributeMaxDynamicSharedMemorySize,
                         smem1);

    k_deg<<<GB_E4, 256>>>(ei);
    k_off<<<NB, 256>>>();
    k_reorder<<<GB_E4, 256>>>(ei);
    k_gemm1<<<(NN + 63) / 64, 128, smem1>>>(x, W1);
    k_gather<1><<<(NN + 7) / 8, 256>>>(b1, nullptr);
    k_gemm2<<<(NN + 63) / 64, 128>>>(W2);
    k_gather<2><<<(NN + 7) / 8, 256>>>(b2, out);
}

// round 10
// speedup vs baseline: 1.2211x; 1.0339x over previous
#include <cuda_runtime.h>

#define NN 50000
#define NE 800000
#define CIN 128
#define CH 64
#define NB 196      // ceil(NN/256)
#define GB_E4 782   // ceil(NE/1024): edge kernels, 4 edges/thread
#define KC 32       // GEMM K-chunk

// ---------------- scratch (no allocs allowed -> device globals) ----------------
__device__ int   g_cnt[NN];        // in-degree histogram; self-cleaned by k_off
__device__ int   g_off[NN];        // CSR segment start per node
__device__ int   g_end[NN];        // CSR segment end per node
__device__ int   g_cur[NN];        // reorder cursors
__device__ float g_dis[NN];        // rsqrt(deg+1)
__device__ int   g_eidx[NE];       // dst-grouped src indices (CSR adjacency)
__device__ int   g_total;          // atomic base counter (reset by k_deg block 0)
__device__ float g_h1[(size_t)NN * CH];   // dis[i] * (x @ W1)
__device__ float g_acc1[(size_t)NN * CH]; // layer-1 output (post-bias, pre-ReLU)
__device__ float g_h2[(size_t)NN * CH];   // dis[i] * (relu(acc1) @ W2)

// ---------------- packed f32x2 helpers ----------------
__device__ __forceinline__ unsigned long long pack_dup(float v) {
    unsigned long long r;
    asm("mov.b64 %0, {%1, %1};" : "=l"(r) : "r"(__float_as_uint(v)));
    return r;
}
__device__ __forceinline__ void ffma2(unsigned long long& d, unsigned long long a,
                                      unsigned long long b) {
    asm("fma.rn.f32x2 %0, %1, %2, %3;" : "=l"(d) : "l"(a), "l"(b), "l"(d));
}
__device__ __forceinline__ unsigned long long fmul2(unsigned long long a,
                                                    unsigned long long b) {
    unsigned long long r;
    asm("mul.rn.f32x2 %0, %1, %2;" : "=l"(r) : "l"(a), "l"(b));
    return r;
}

// per-block int64-vs-int32 detection (reads 16 leading entries; L2-hot)
__device__ __forceinline__ int detect64(const void* idx) {
    const long long* p = (const long long*)idx;
    int ok = 1;
    for (int j = 0; j < 16; j++) {
        long long v = p[j];
        if (v < 0 || v >= NN) ok = 0;
    }
    return ok;
}

// ---------------- degree histogram: 4 edges/thread, vectorized ----------------
__global__ __launch_bounds__(256) void k_deg(const void* __restrict__ idx) {
    __shared__ int s64;
    const int t = threadIdx.x;
    if (t == 0) {
        s64 = detect64(idx);
        if (blockIdx.x == 0) g_total = 0;  // reset base counter for k_off
    }
    __syncthreads();
    int e0 = (blockIdx.x * 256 + t) * 4;
    if (e0 >= NE) return;  // NE%4==0 -> full quad
    int d0, d1, d2, d3;
    if (s64) {
        const ulonglong2* pd = (const ulonglong2*)((const long long*)idx + NE + e0);
        ulonglong2 a = __ldg(pd), b = __ldg(pd + 1);
        d0 = (int)a.x; d1 = (int)a.y; d2 = (int)b.x; d3 = (int)b.y;
    } else {
        int4 dv = __ldg((const int4*)((const int*)idx + NE + e0));
        d0 = dv.x; d1 = dv.y; d2 = dv.z; d3 = dv.w;
    }
    atomicAdd(&g_cnt[d0], 1);
    atomicAdd(&g_cnt[d1], 1);
    atomicAdd(&g_cnt[d2], 1);
    atomicAdd(&g_cnt[d3], 1);
}

// ---------------- fused offsets: block scan + atomic block base ----------------
__global__ __launch_bounds__(256) void k_off() {
    __shared__ int sm[256];
    __shared__ int sbase;
    const int t = threadIdx.x;
    int i = blockIdx.x * 256 + t;
    int c = (i < NN) ? g_cnt[i] : 0;
    sm[t] = c;
    __syncthreads();
    for (int o = 1; o < 256; o <<= 1) {
        int u = (t >= o) ? sm[t - o] : 0;
        __syncthreads();
        sm[t] += u;
        __syncthreads();
    }
    if (t == 255) sbase = atomicAdd(&g_total, sm[255]);
    __syncthreads();
    int off = sbase + sm[t] - c;
    if (i < NN) {
        g_off[i] = off;
        g_end[i] = off + c;
        g_cur[i] = off;
        g_dis[i] = rsqrtf((float)(c + 1));  // degree includes self-loop
        g_cnt[i] = 0;                       // clean for next call
    }
}

// ---------------- reorder: 4 edges/thread, reads edge_index directly ----------------
__global__ __launch_bounds__(256) void k_reorder(const void* __restrict__ idx) {
    __shared__ int s64;
    const int t = threadIdx.x;
    if (t == 0) s64 = detect64(idx);
    __syncthreads();
    int e0 = (blockIdx.x * 256 + t) * 4;
    if (e0 >= NE) return;
    int s0, s1, s2, s3, d0, d1, d2, d3;
    if (s64) {
        const long long* p = (const long long*)idx;
        ulonglong2 a = __ldg((const ulonglong2*)(p + e0));
        ulonglong2 b = __ldg((const ulonglong2*)(p + e0) + 1);
        ulonglong2 c = __ldg((const ulonglong2*)(p + NE + e0));
        ulonglong2 d = __ldg((const ulonglong2*)(p + NE + e0) + 1);
        s0 = (int)a.x; s1 = (int)a.y; s2 = (int)b.x; s3 = (int)b.y;
        d0 = (int)c.x; d1 = (int)c.y; d2 = (int)d.x; d3 = (int)d.y;
    } else {
        const int* p = (const int*)idx;
        int4 a = __ldg((const int4*)(p + e0));
        int4 c = __ldg((const int4*)(p + NE + e0));
        s0 = a.x; s1 = a.y; s2 = a.z; s3 = a.w;
        d0 = c.x; d1 = c.y; d2 = c.z; d3 = c.w;
    }
    int p0 = atomicAdd(&g_cur[d0], 1);
    int p1 = atomicAdd(&g_cur[d1], 1);
    int p2 = atomicAdd(&g_cur[d2], 1);
    int p3 = atomicAdd(&g_cur[d3], 1);
    g_eidx[p0] = s0;
    g_eidx[p1] = s1;
    g_eidx[p2] = s2;
    g_eidx[p3] = s3;
}

// ---------------- GEMM1: h1 = dis[row] * (x @ W1), K-chunked, 16.7KB smem ----------------
// 128 thr, 64x64 tile, 4x8 thread tile, f32x2. KC=32 chunks -> ~8 CTAs/SM (50% occ).
__global__ __launch_bounds__(128) void k_gemm1(const float* __restrict__ x,
                                               const float* __restrict__ W) {
    __shared__ float Ws[KC * CH];   // [k][n], 8KB
    __shared__ float Xs[64 * 34];   // [row][k] pad 34, 8.7KB
    const int t = threadIdx.x;
    const int row0 = blockIdx.x * 64;
    const int tx = t & 7;
    const int ty = t >> 3;

    unsigned long long acc[4][4];
    #pragma unroll
    for (int r = 0; r < 4; r++)
        #pragma unroll
        for (int p = 0; p < 4; p++) acc[r][p] = 0ull;

    for (int kc = 0; kc < CIN; kc += KC) {
        __syncthreads();  // previous chunk fully consumed
        {   // W chunk: rows kc..kc+31, contiguous 512 float4
            const float4* Wg = (const float4*)(W + kc * CH);
            float4* Wsv = (float4*)Ws;
            #pragma unroll
            for (int i = 0; i < 4; i++) Wsv[i * 128 + t] = Wg[i * 128 + t];
        }
        #pragma unroll
        for (int i = 0; i < 4; i++) {  // X chunk: 64 rows x 32 k
            int idx = i * 128 + t;
            int r = idx >> 3, c4 = idx & 7;
            int gr = row0 + r;
            float4 v = (gr < NN)
                ? __ldg((const float4*)(x + (size_t)gr * CIN + kc) + c4)
                : make_float4(0.f, 0.f, 0.f, 0.f);
            float* xp = Xs + r * 34 + c4 * 4;
            xp[0] = v.x; xp[1] = v.y; xp[2] = v.z; xp[3] = v.w;
        }
        __syncthreads();

        const float* Xp = Xs + ty * 4 * 34;
        const float* Wp = Ws + tx * 8;
        #pragma unroll 4
        for (int k = 0; k < KC; k++) {
            ulonglong2 w01 = *(const ulonglong2*)(Wp + k * CH);
            ulonglong2 w23 = *(const ulonglong2*)(Wp + k * CH + 4);
            #pragma unroll
            for (int r = 0; r < 4; r++) {
                unsigned long long xx = pack_dup(Xp[r * 34 + k]);
                ffma2(acc[r][0], xx, w01.x);
                ffma2(acc[r][1], xx, w01.y);
                ffma2(acc[r][2], xx, w23.x);
                ffma2(acc[r][3], xx, w23.y);
            }
        }
    }

    #pragma unroll
    for (int r = 0; r < 4; r++) {
        int gr = row0 + ty * 4 + r;
        if (gr < NN) {
            unsigned long long dd = pack_dup(g_dis[gr]);
            float* hp = g_h1 + (size_t)gr * CH + tx * 8;
            *(ulonglong2*)hp = make_ulonglong2(fmul2(acc[r][0], dd), fmul2(acc[r][1], dd));
            *(ulonglong2*)(hp + 4) = make_ulonglong2(fmul2(acc[r][2], dd), fmul2(acc[r][3], dd));
        }
    }
}

// ---------------- GEMM2: h2 = dis[row] * (relu(acc1) @ W2), K-chunked ----------------
__global__ __launch_bounds__(128) void k_gemm2(const float* __restrict__ W) {
    __shared__ float Ws[KC * CH];
    __shared__ float Xs[64 * 34];
    const int t = threadIdx.x;
    const int row0 = blockIdx.x * 64;
    const int tx = t & 7;
    const int ty = t >> 3;

    unsigned long long acc[4][4];
    #pragma unroll
    for (int r = 0; r < 4; r++)
        #pragma unroll
        for (int p = 0; p < 4; p++) acc[r][p] = 0ull;

    for (int kc = 0; kc < CH; kc += KC) {
        __syncthreads();
        {
            const float4* Wg = (const float4*)(W + kc * CH);
            float4* Wsv = (float4*)Ws;
            #pragma unroll
            for (int i = 0; i < 4; i++) Wsv[i * 128 + t] = Wg[i * 128 + t];
        }
        #pragma unroll
        for (int i = 0; i < 4; i++) {
            int idx = i * 128 + t;
            int r = idx >> 3, c4 = idx & 7;
            int gr = row0 + r;
            float4 v = (gr < NN)
                ? *(const float4*)(g_acc1 + (size_t)gr * CH + kc + c4 * 4)
                : make_float4(0.f, 0.f, 0.f, 0.f);
            float* xp = Xs + r * 34 + c4 * 4;
            xp[0] = fmaxf(v.x, 0.f);  // fused ReLU
            xp[1] = fmaxf(v.y, 0.f);
            xp[2] = fmaxf(v.z, 0.f);
            xp[3] = fmaxf(v.w, 0.f);
        }
        __syncthreads();

        const float* Xp = Xs + ty * 4 * 34;
        const float* Wp = Ws + tx * 8;
        #pragma unroll 4
        for (int k = 0; k < KC; k++) {
            ulonglong2 w01 = *(const ulonglong2*)(Wp + k * CH);
            ulonglong2 w23 = *(const ulonglong2*)(Wp + k * CH + 4);
            #pragma unroll
            for (int r = 0; r < 4; r++) {
                unsigned long long xx = pack_dup(Xp[r * 34 + k]);
                ffma2(acc[r][0], xx, w01.x);
                ffma2(acc[r][1], xx, w01.y);
                ffma2(acc[r][2], xx, w23.x);
                ffma2(acc[r][3], xx, w23.y);
            }
        }
    }

    #pragma unroll
    for (int r = 0; r < 4; r++) {
        int gr = row0 + ty * 4 + r;
        if (gr < NN) {
            unsigned long long dd = pack_dup(g_dis[gr]);
            float* hp = g_h2 + (size_t)gr * CH + tx * 8;
            *(ulonglong2*)hp = make_ulonglong2(fmul2(acc[r][0], dd), fmul2(acc[r][1], dd));
            *(ulonglong2*)(hp + 4) = make_ulonglong2(fmul2(acc[r][2], dd), fmul2(acc[r][3], dd));
        }
    }
}

// ---------------- CSR gather: dst[i] = dis[i]*(hs[i] + sum_e hs[src_e]) + b ----------------
// hs pre-scaled by dis -> pure adds per edge. One warp/node, lane owns 2 cols,
// 4x unrolled for MLP. Destination chosen in device code (never pass a
// __device__ symbol as a host-side kernel arg).
template <int L>
__global__ __launch_bounds__(256) void k_gather(const float* __restrict__ b,
                                                float* __restrict__ out_arg) {
    const int node = blockIdx.x * 8 + (threadIdx.x >> 5);
    const int lane = threadIdx.x & 31;
    if (node >= NN) return;
    const float* __restrict__ hs = (L == 1) ? g_h1 : g_h2;
    float* __restrict__ dst = (L == 1) ? g_acc1 : out_arg;

    float2 acc = __ldg((const float2*)(hs + (size_t)node * CH) + lane);  // self term

    int e = g_off[node];
    const int s1 = g_end[node];
    for (; e + 4 <= s1; e += 4) {
        int sj0 = __ldg(g_eidx + e);
        int sj1 = __ldg(g_eidx + e + 1);
        int sj2 = __ldg(g_eidx + e + 2);
        int sj3 = __ldg(g_eidx + e + 3);
        float2 v0 = __ldg((const float2*)(hs + (size_t)sj0 * CH) + lane);
        float2 v1 = __ldg((const float2*)(hs + (size_t)sj1 * CH) + lane);
        float2 v2 = __ldg((const float2*)(hs + (size_t)sj2 * CH) + lane);
        float2 v3 = __ldg((const float2*)(hs + (size_t)sj3 * CH) + lane);
        acc.x += v0.x + v1.x + v2.x + v3.x;
        acc.y += v0.y + v1.y + v2.y + v3.y;
    }
    for (; e < s1; e++) {
        int sj = __ldg(g_eidx + e);
        float2 v = __ldg((const float2*)(hs + (size_t)sj * CH) + lane);
        acc.x += v.x;
        acc.y += v.y;
    }

    float ds = g_dis[node];
    float2 bv = __ldg((const float2*)b + lane);
    float2 o;
    o.x = ds * acc.x + bv.x;
    o.y = ds * acc.y + bv.y;
    *((float2*)(dst + (size_t)node * CH) + lane) = o;
}

// ---------------- launch ----------------
extern "C" void kernel_launch(void* const* d_in, const int* in_sizes, int n_in,
                              void* d_out, int out_size) {
    const float* x  = (const float*)d_in[0];
    const void*  ei = d_in[1];
    const float* W1 = (const float*)d_in[2];
    const float* b1 = (const float*)d_in[3];
    const float* W2 = (const float*)d_in[4];
    const float* b2 = (const float*)d_in[5];
    float* out = (float*)d_out;

    k_deg<<<GB_E4, 256>>>(ei);
    k_off<<<NB, 256>>>();
    k_reorder<<<GB_E4, 256>>>(ei);
    k_gemm1<<<(NN + 63) / 64, 128>>>(x, W1);
    k_gather<1><<<(NN + 7) / 8, 256>>>(b1, nullptr);
    k_gemm2<<<(NN + 63) / 64, 128>>>(W2);
    k_gather<2><<<(NN + 7) / 8, 256>>>(b2, out);
}

// round 11
// speedup vs baseline: 1.3763x; 1.1271x over previous
#include <cuda_runtime.h>

#define NN 50000
#define NE 800000
#define CIN 128
#define CH 64
#define NB 196      // ceil(NN/256)
#define GB_E4 782   // ceil(NE/1024): edge kernels, 4 edges/thread
#define KC 32       // GEMM K-chunk
#define XS_STR 132  // Xs row stride (floats), 16B-aligned, bank-staggered

// ---------------- scratch (no allocs allowed -> device globals) ----------------
__device__ int   g_cnt[NN];        // in-degree histogram; self-cleaned by k_off
__device__ int   g_off[NN];        // CSR segment start per node
__device__ int   g_end[NN];        // CSR segment end per node
__device__ int   g_cur[NN];        // reorder cursors
__device__ float g_dis[NN];        // rsqrt(deg+1)
__device__ int   g_eidx[NE];       // dst-grouped src indices (CSR adjacency)
__device__ int   g_total;          // atomic base counter (reset by k_deg block 0)
__device__ float g_h1[(size_t)NN * CH];   // dis[i] * (x @ W1)
__device__ float g_acc1[(size_t)NN * CH]; // layer-1 output (post-bias, pre-ReLU)
__device__ float g_h2[(size_t)NN * CH];   // dis[i] * (relu(acc1) @ W2)

// ---------------- packed f32x2 helpers ----------------
__device__ __forceinline__ unsigned long long pack_dup(float v) {
    unsigned long long r;
    asm("mov.b64 %0, {%1, %1};" : "=l"(r) : "r"(__float_as_uint(v)));
    return r;
}
__device__ __forceinline__ void ffma2(unsigned long long& d, unsigned long long a,
                                      unsigned long long b) {
    asm("fma.rn.f32x2 %0, %1, %2, %3;" : "=l"(d) : "l"(a), "l"(b), "l"(d));
}
__device__ __forceinline__ unsigned long long fmul2(unsigned long long a,
                                                    unsigned long long b) {
    unsigned long long r;
    asm("mul.rn.f32x2 %0, %1, %2;" : "=l"(r) : "l"(a), "l"(b));
    return r;
}

// per-block int64-vs-int32 detection (reads 16 leading entries; L2-hot)
__device__ __forceinline__ int detect64(const void* idx) {
    const long long* p = (const long long*)idx;
    int ok = 1;
    for (int j = 0; j < 16; j++) {
        long long v = p[j];
        if (v < 0 || v >= NN) ok = 0;
    }
    return ok;
}

// ---------------- degree histogram: 4 edges/thread, vectorized ----------------
__global__ __launch_bounds__(256) void k_deg(const void* __restrict__ idx) {
    __shared__ int s64;
    const int t = threadIdx.x;
    if (t == 0) {
        s64 = detect64(idx);
        if (blockIdx.x == 0) g_total = 0;  // reset base counter for k_off
    }
    __syncthreads();
    int e0 = (blockIdx.x * 256 + t) * 4;
    if (e0 >= NE) return;  // NE%4==0 -> full quad
    int d0, d1, d2, d3;
    if (s64) {
        const ulonglong2* pd = (const ulonglong2*)((const long long*)idx + NE + e0);
        ulonglong2 a = __ldg(pd), b = __ldg(pd + 1);
        d0 = (int)a.x; d1 = (int)a.y; d2 = (int)b.x; d3 = (int)b.y;
    } else {
        int4 dv = __ldg((const int4*)((const int*)idx + NE + e0));
        d0 = dv.x; d1 = dv.y; d2 = dv.z; d3 = dv.w;
    }
    atomicAdd(&g_cnt[d0], 1);
    atomicAdd(&g_cnt[d1], 1);
    atomicAdd(&g_cnt[d2], 1);
    atomicAdd(&g_cnt[d3], 1);
}

// ---------------- fused offsets: block scan + atomic block base ----------------
__global__ __launch_bounds__(256) void k_off() {
    __shared__ int sm[256];
    __shared__ int sbase;
    const int t = threadIdx.x;
    int i = blockIdx.x * 256 + t;
    int c = (i < NN) ? g_cnt[i] : 0;
    sm[t] = c;
    __syncthreads();
    for (int o = 1; o < 256; o <<= 1) {
        int u = (t >= o) ? sm[t - o] : 0;
        __syncthreads();
        sm[t] += u;
        __syncthreads();
    }
    if (t == 255) sbase = atomicAdd(&g_total, sm[255]);
    __syncthreads();
    int off = sbase + sm[t] - c;
    if (i < NN) {
        g_off[i] = off;
        g_end[i] = off + c;
        g_cur[i] = off;
        g_dis[i] = rsqrtf((float)(c + 1));  // degree includes self-loop
        g_cnt[i] = 0;                       // clean for next call
    }
}

// ---------------- reorder: 4 edges/thread, reads edge_index directly ----------------
__global__ __launch_bounds__(256) void k_reorder(const void* __restrict__ idx) {
    __shared__ int s64;
    const int t = threadIdx.x;
    if (t == 0) s64 = detect64(idx);
    __syncthreads();
    int e0 = (blockIdx.x * 256 + t) * 4;
    if (e0 >= NE) return;
    int s0, s1, s2, s3, d0, d1, d2, d3;
    if (s64) {
        const long long* p = (const long long*)idx;
        ulonglong2 a = __ldg((const ulonglong2*)(p + e0));
        ulonglong2 b = __ldg((const ulonglong2*)(p + e0) + 1);
        ulonglong2 c = __ldg((const ulonglong2*)(p + NE + e0));
        ulonglong2 d = __ldg((const ulonglong2*)(p + NE + e0) + 1);
        s0 = (int)a.x; s1 = (int)a.y; s2 = (int)b.x; s3 = (int)b.y;
        d0 = (int)c.x; d1 = (int)c.y; d2 = (int)d.x; d3 = (int)d.y;
    } else {
        const int* p = (const int*)idx;
        int4 a = __ldg((const int4*)(p + e0));
        int4 c = __ldg((const int4*)(p + NE + e0));
        s0 = a.x; s1 = a.y; s2 = a.z; s3 = a.w;
        d0 = c.x; d1 = c.y; d2 = c.z; d3 = c.w;
    }
    int p0 = atomicAdd(&g_cur[d0], 1);
    int p1 = atomicAdd(&g_cur[d1], 1);
    int p2 = atomicAdd(&g_cur[d2], 1);
    int p3 = atomicAdd(&g_cur[d3], 1);
    g_eidx[p0] = s0;
    g_eidx[p1] = s1;
    g_eidx[p2] = s2;
    g_eidx[p3] = s3;
}

// ---------------- GEMM inner: 8x8 thread tile over one K-chunk ----------------
// Xs k-major [KC][XS_STR]; Ws [KC][CH]. Per k: 2+2 LDS.128, 32 FFMA2 (1:8).
__device__ __forceinline__ void gemm_chunk(const float* __restrict__ Ws,
                                           const float* __restrict__ Xs,
                                           int tx, int ty,
                                           unsigned long long acc[8][4]) {
    const float* Wp = Ws + tx * 8;
    const float* Xp = Xs + ty * 8;
    #pragma unroll 4
    for (int k = 0; k < KC; k++) {
        ulonglong2 w01 = *(const ulonglong2*)(Wp + k * CH);
        ulonglong2 w23 = *(const ulonglong2*)(Wp + k * CH + 4);
        float4 xa = *(const float4*)(Xp + k * XS_STR);
        float4 xb = *(const float4*)(Xp + k * XS_STR + 4);
        float xr[8] = {xa.x, xa.y, xa.z, xa.w, xb.x, xb.y, xb.z, xb.w};
        #pragma unroll
        for (int r = 0; r < 8; r++) {
            unsigned long long xx = pack_dup(xr[r]);
            ffma2(acc[r][0], xx, w01.x);
            ffma2(acc[r][1], xx, w01.y);
            ffma2(acc[r][2], xx, w23.x);
            ffma2(acc[r][3], xx, w23.y);
        }
    }
}

// ---------------- GEMM1: h1 = dis[row] * (x @ W1), 128x64 tile, 8x8/thread ----------------
__global__ __launch_bounds__(128) void k_gemm1(const float* __restrict__ x,
                                               const float* __restrict__ W) {
    __shared__ float Ws[KC * CH];      // 8KB
    __shared__ float Xs[KC * XS_STR];  // 16.9KB, k-major
    const int t = threadIdx.x;
    const int row0 = blockIdx.x * 128;
    const int tx = t & 7;
    const int ty = t >> 3;  // 0..15, owns rows ty*8..ty*8+7

    unsigned long long acc[8][4];
    #pragma unroll
    for (int r = 0; r < 8; r++)
        #pragma unroll
        for (int p = 0; p < 4; p++) acc[r][p] = 0ull;

    for (int kc = 0; kc < CIN; kc += KC) {
        __syncthreads();  // previous chunk fully consumed
        {   // W chunk: 32x64 = 512 float4
            const float4* Wg = (const float4*)(W + kc * CH);
            float4* Wsv = (float4*)Ws;
            #pragma unroll
            for (int i = 0; i < 4; i++) Wsv[i * 128 + t] = Wg[i * 128 + t];
        }
        #pragma unroll
        for (int i = 0; i < 8; i++) {  // X chunk: 128 rows x 32 k, transpose to k-major
            int idx = i * 128 + t;
            int row = idx >> 3, c4 = idx & 7;
            int gr = row0 + row;
            float4 v = (gr < NN)
                ? __ldg((const float4*)(x + (size_t)gr * CIN + kc) + c4)
                : make_float4(0.f, 0.f, 0.f, 0.f);
            int kb = c4 * 4;
            Xs[(kb + 0) * XS_STR + row] = v.x;
            Xs[(kb + 1) * XS_STR + row] = v.y;
            Xs[(kb + 2) * XS_STR + row] = v.z;
            Xs[(kb + 3) * XS_STR + row] = v.w;
        }
        __syncthreads();
        gemm_chunk(Ws, Xs, tx, ty, acc);
    }

    #pragma unroll
    for (int r = 0; r < 8; r++) {
        int gr = row0 + ty * 8 + r;
        if (gr < NN) {
            unsigned long long dd = pack_dup(g_dis[gr]);
            float* hp = g_h1 + (size_t)gr * CH + tx * 8;
            *(ulonglong2*)hp = make_ulonglong2(fmul2(acc[r][0], dd), fmul2(acc[r][1], dd));
            *(ulonglong2*)(hp + 4) = make_ulonglong2(fmul2(acc[r][2], dd), fmul2(acc[r][3], dd));
        }
    }
}

// ---------------- GEMM2: h2 = dis[row] * (relu(acc1) @ W2), same structure ----------------
__global__ __launch_bounds__(128) void k_gemm2(const float* __restrict__ W) {
    __shared__ float Ws[KC * CH];
    __shared__ float Xs[KC * XS_STR];
    const int t = threadIdx.x;
    const int row0 = blockIdx.x * 128;
    const int tx = t & 7;
    const int ty = t >> 3;

    unsigned long long acc[8][4];
    #pragma unroll
    for (int r = 0; r < 8; r++)
        #pragma unroll
        for (int p = 0; p < 4; p++) acc[r][p] = 0ull;

    for (int kc = 0; kc < CH; kc += KC) {
        __syncthreads();
        {
            const float4* Wg = (const float4*)(W + kc * CH);
            float4* Wsv = (float4*)Ws;
            #pragma unroll
            for (int i = 0; i < 4; i++) Wsv[i * 128 + t] = Wg[i * 128 + t];
        }
        #pragma unroll
        for (int i = 0; i < 8; i++) {  // 128 rows x 32 k from g_acc1, fused ReLU
            int idx = i * 128 + t;
            int row = idx >> 3, c4 = idx & 7;
            int gr = row0 + row;
            float4 v = (gr < NN)
                ? *(const float4*)(g_acc1 + (size_t)gr * CH + kc + c4 * 4)
                : make_float4(0.f, 0.f, 0.f, 0.f);
            int kb = c4 * 4;
            Xs[(kb + 0) * XS_STR + row] = fmaxf(v.x, 0.f);
            Xs[(kb + 1) * XS_STR + row] = fmaxf(v.y, 0.f);
            Xs[(kb + 2) * XS_STR + row] = fmaxf(v.z, 0.f);
            Xs[(kb + 3) * XS_STR + row] = fmaxf(v.w, 0.f);
        }
        __syncthreads();
        gemm_chunk(Ws, Xs, tx, ty, acc);
    }

    #pragma unroll
    for (int r = 0; r < 8; r++) {
        int gr = row0 + ty * 8 + r;
        if (gr < NN) {
            unsigned long long dd = pack_dup(g_dis[gr]);
            float* hp = g_h2 + (size_t)gr * CH + tx * 8;
            *(ulonglong2*)hp = make_ulonglong2(fmul2(acc[r][0], dd), fmul2(acc[r][1], dd));
            *(ulonglong2*)(hp + 4) = make_ulonglong2(fmul2(acc[r][2], dd), fmul2(acc[r][3], dd));
        }
    }
}

// ---------------- CSR gather: dst[i] = dis[i]*(hs[i] + sum_e hs[src_e]) + b ----------------
template <int L>
__global__ __launch_bounds__(256) void k_gather(const float* __restrict__ b,
                                                float* __restrict__ out_arg) {
    const int node = blockIdx.x * 8 + (threadIdx.x >> 5);
    const int lane = threadIdx.x & 31;
    if (node >= NN) return;
    const float* __restrict__ hs = (L == 1) ? g_h1 : g_h2;
    float* __restrict__ dst = (L == 1) ? g_acc1 : out_arg;

    float2 acc = __ldg((const float2*)(hs + (size_t)node * CH) + lane);  // self term

    int e = g_off[node];
    const int s1 = g_end[node];
    for (; e + 4 <= s1; e += 4) {
        int sj0 = __ldg(g_eidx + e);
        int sj1 = __ldg(g_eidx + e + 1);
        int sj2 = __ldg(g_eidx + e + 2);
        int sj3 = __ldg(g_eidx + e + 3);
        float2 v0 = __ldg((const float2*)(hs + (size_t)sj0 * CH) + lane);
        float2 v1 = __ldg((const float2*)(hs + (size_t)sj1 * CH) + lane);
        float2 v2 = __ldg((const float2*)(hs + (size_t)sj2 * CH) + lane);
        float2 v3 = __ldg((const float2*)(hs + (size_t)sj3 * CH) + lane);
        acc.x += v0.x + v1.x + v2.x + v3.x;
        acc.y += v0.y + v1.y + v2.y + v3.y;
    }
    for (; e < s1; e++) {
        int sj = __ldg(g_eidx + e);
        float2 v = __ldg((const float2*)(hs + (size_t)sj * CH) + lane);
        acc.x += v.x;
        acc.y += v.y;
    }

    float ds = g_dis[node];
    float2 bv = __ldg((const float2*)b + lane);
    float2 o;
    o.x = ds * acc.x + bv.x;
    o.y = ds * acc.y + bv.y;
    *((float2*)(dst + (size_t)node * CH) + lane) = o;
}

// ---------------- launch ----------------
extern "C" void kernel_launch(void* const* d_in, const int* in_sizes, int n_in,
                              void* d_out, int out_size) {
    const float* x  = (const float*)d_in[0];
    const void*  ei = d_in[1];
    const float* W1 = (const float*)d_in[2];
    const float* b1 = (const float*)d_in[3];
    const float* W2 = (const float*)d_in[4];
    const float* b2 = (const float*)d_in[5];
    float* out = (float*)d_out;

    k_deg<<<GB_E4, 256>>>(ei);
    k_off<<<NB, 256>>>();
    k_reorder<<<GB_E4, 256>>>(ei);
    k_gemm1<<<(NN + 127) / 128, 128>>>(x, W1);
    k_gather<1><<<(NN + 7) / 8, 256>>>(b1, nullptr);
    k_gemm2<<<(NN + 127) / 128, 128>>>(W2);
    k_gather<2><<<(NN + 7) / 8, 256>>>(b2, out);
}

// round 12
// speedup vs baseline: 1.3792x; 1.0021x over previous
#include <cuda_runtime.h>
#include <cstdint>

#define NN 50000
#define NE 800000
#define CIN 128
#define CH 64
#define NB 196      // ceil(NN/256)
#define GB_E4 782   // ceil(NE/1024): edge kernels, 4 edges/thread
#define KC2 16      // GEMM K-chunk (two k8 steps)
#define XSTR 20     // Xs row stride (floats): conflict-free A-frag loads
#define WSTR 72     // Ws row stride (floats): conflict-free B-frag loads

// ---------------- scratch (no allocs allowed -> device globals) ----------------
__device__ int   g_cnt[NN];        // in-degree histogram; self-cleaned by k_off
__device__ int   g_off[NN];        // CSR segment start per node
__device__ int   g_end[NN];        // CSR segment end per node
__device__ int   g_cur[NN];        // reorder cursors
__device__ float g_dis[NN];        // rsqrt(deg+1)
__device__ int   g_eidx[NE];       // dst-grouped src indices (CSR adjacency)
__device__ int   g_total;          // atomic base counter (reset by k_deg block 0)
__device__ float g_h1[(size_t)NN * CH];   // dis[i] * (x @ W1)
__device__ float g_acc1[(size_t)NN * CH]; // layer-1 output (post-bias, pre-ReLU)
__device__ float g_h2[(size_t)NN * CH];   // dis[i] * (relu(acc1) @ W2)

// ---------------- tf32 helpers ----------------
__device__ __forceinline__ uint32_t to_tf32(float x) {
    uint32_t r;
    asm("cvt.rna.tf32.f32 %0, %1;" : "=r"(r) : "f"(x));
    return r;
}
// split x into hi (tf32) + lo (tf32 of exact residual)
__device__ __forceinline__ void tf32_split(float x, float& hi, float& lo) {
    uint32_t h = to_tf32(x);
    hi = __uint_as_float(h);
    lo = __uint_as_float(to_tf32(x - hi));
}
__device__ __forceinline__ void mma_tf32(float c[4], const uint32_t a[4],
                                         const uint32_t b[2]) {
    asm volatile(
        "mma.sync.aligned.m16n8k8.row.col.f32.tf32.tf32.f32 "
        "{%0,%1,%2,%3}, {%4,%5,%6,%7}, {%8,%9}, {%0,%1,%2,%3};"
        : "+f"(c[0]), "+f"(c[1]), "+f"(c[2]), "+f"(c[3])
        : "r"(a[0]), "r"(a[1]), "r"(a[2]), "r"(a[3]), "r"(b[0]), "r"(b[1]));
}

// per-block int64-vs-int32 detection (reads 16 leading entries; L2-hot)
__device__ __forceinline__ int detect64(const void* idx) {
    const long long* p = (const long long*)idx;
    int ok = 1;
    for (int j = 0; j < 16; j++) {
        long long v = p[j];
        if (v < 0 || v >= NN) ok = 0;
    }
    return ok;
}

// ---------------- degree histogram: 4 edges/thread, vectorized ----------------
__global__ __launch_bounds__(256) void k_deg(const void* __restrict__ idx) {
    __shared__ int s64;
    const int t = threadIdx.x;
    if (t == 0) {
        s64 = detect64(idx);
        if (blockIdx.x == 0) g_total = 0;
    }
    __syncthreads();
    int e0 = (blockIdx.x * 256 + t) * 4;
    if (e0 >= NE) return;
    int d0, d1, d2, d3;
    if (s64) {
        const ulonglong2* pd = (const ulonglong2*)((const long long*)idx + NE + e0);
        ulonglong2 a = __ldg(pd), b = __ldg(pd + 1);
        d0 = (int)a.x; d1 = (int)a.y; d2 = (int)b.x; d3 = (int)b.y;
    } else {
        int4 dv = __ldg((const int4*)((const int*)idx + NE + e0));
        d0 = dv.x; d1 = dv.y; d2 = dv.z; d3 = dv.w;
    }
    atomicAdd(&g_cnt[d0], 1);
    atomicAdd(&g_cnt[d1], 1);
    atomicAdd(&g_cnt[d2], 1);
    atomicAdd(&g_cnt[d3], 1);
}

// ---------------- fused offsets: block scan + atomic block base ----------------
__global__ __launch_bounds__(256) void k_off() {
    __shared__ int sm[256];
    __shared__ int sbase;
    const int t = threadIdx.x;
    int i = blockIdx.x * 256 + t;
    int c = (i < NN) ? g_cnt[i] : 0;
    sm[t] = c;
    __syncthreads();
    for (int o = 1; o < 256; o <<= 1) {
        int u = (t >= o) ? sm[t - o] : 0;
        __syncthreads();
        sm[t] += u;
        __syncthreads();
    }
    if (t == 255) sbase = atomicAdd(&g_total, sm[255]);
    __syncthreads();
    int off = sbase + sm[t] - c;
    if (i < NN) {
        g_off[i] = off;
        g_end[i] = off + c;
        g_cur[i] = off;
        g_dis[i] = rsqrtf((float)(c + 1));
        g_cnt[i] = 0;
    }
}

// ---------------- reorder: 4 edges/thread, reads edge_index directly ----------------
__global__ __launch_bounds__(256) void k_reorder(const void* __restrict__ idx) {
    __shared__ int s64;
    const int t = threadIdx.x;
    if (t == 0) s64 = detect64(idx);
    __syncthreads();
    int e0 = (blockIdx.x * 256 + t) * 4;
    if (e0 >= NE) return;
    int s0, s1, s2, s3, d0, d1, d2, d3;
    if (s64) {
        const long long* p = (const long long*)idx;
        ulonglong2 a = __ldg((const ulonglong2*)(p + e0));
        ulonglong2 b = __ldg((const ulonglong2*)(p + e0) + 1);
        ulonglong2 c = __ldg((const ulonglong2*)(p + NE + e0));
        ulonglong2 d = __ldg((const ulonglong2*)(p + NE + e0) + 1);
        s0 = (int)a.x; s1 = (int)a.y; s2 = (int)b.x; s3 = (int)b.y;
        d0 = (int)c.x; d1 = (int)c.y; d2 = (int)d.x; d3 = (int)d.y;
    } else {
        const int* p = (const int*)idx;
        int4 a = __ldg((const int4*)(p + e0));
        int4 c = __ldg((const int4*)(p + NE + e0));
        s0 = a.x; s1 = a.y; s2 = a.z; s3 = a.w;
        d0 = c.x; d1 = c.y; d2 = c.z; d3 = c.w;
    }
    int p0 = atomicAdd(&g_cur[d0], 1);
    int p1 = atomicAdd(&g_cur[d1], 1);
    int p2 = atomicAdd(&g_cur[d2], 1);
    int p3 = atomicAdd(&g_cur[d3], 1);
    g_eidx[p0] = s0;
    g_eidx[p1] = s1;
    g_eidx[p2] = s2;
    g_eidx[p3] = s3;
}

// ---------------- tensor-core GEMM body (3xtf32) ----------------
// Block 128(M)x64(N), 256 thr = 8 warps as 4(M)x2(N); warp tile 32x32
// (2 m16 x 4 n8). KSTEPS = K/KC2 chunks, two k8 per chunk.
// IN==1: read x (row stride CIN); IN==2: read relu(g_acc1) (row stride CH).
template <int KTOT, int IN>
__device__ __forceinline__ void gemm_tc(const float* __restrict__ xin,
                                        const float* __restrict__ W,
                                        float* __restrict__ hout) {
    __shared__ float Xh[128 * XSTR], Xl[128 * XSTR];
    __shared__ float Wh[KC2 * WSTR], Wl[KC2 * WSTR];
    const int t = threadIdx.x;
    const int row0 = blockIdx.x * 128;
    const int lane = t & 31;
    const int g = lane >> 2;     // 0..7
    const int tig = lane & 3;    // 0..3
    const int warp = t >> 5;
    const int m0w = (warp & 3) * 32;
    const int n0w = (warp >> 2) * 32;
    const int instr = (IN == 1) ? CIN : CH;

    float acc[2][4][4];
    #pragma unroll
    for (int mt = 0; mt < 2; mt++)
        #pragma unroll
        for (int nt = 0; nt < 4; nt++)
            #pragma unroll
            for (int q = 0; q < 4; q++) acc[mt][nt][q] = 0.0f;

    for (int kc = 0; kc < KTOT; kc += KC2) {
        __syncthreads();
        {   // W chunk: 16 x 64 = 256 float4, 1 per thread
            int k = t >> 4, c4 = t & 15;
            float4 v = __ldg((const float4*)(W + (size_t)(kc + k) * CH) + c4);
            float* ph = Wh + k * WSTR + c4 * 4;
            float* pl = Wl + k * WSTR + c4 * 4;
            tf32_split(v.x, ph[0], pl[0]);
            tf32_split(v.y, ph[1], pl[1]);
            tf32_split(v.z, ph[2], pl[2]);
            tf32_split(v.w, ph[3], pl[3]);
        }
        #pragma unroll
        for (int i = 0; i < 2; i++) {  // X chunk: 128 rows x 16 k = 512 float4
            int fid = i * 256 + t;
            int row = fid >> 2, c4 = fid & 3;
            int gr = row0 + row;
            float4 v = make_float4(0.f, 0.f, 0.f, 0.f);
            if (gr < NN) {
                v = __ldg((const float4*)(xin + (size_t)gr * instr + kc) + c4);
                if (IN == 2) {
                    v.x = fmaxf(v.x, 0.f); v.y = fmaxf(v.y, 0.f);
                    v.z = fmaxf(v.z, 0.f); v.w = fmaxf(v.w, 0.f);
                }
            }
            float* ph = Xh + row * XSTR + c4 * 4;
            float* pl = Xl + row * XSTR + c4 * 4;
            tf32_split(v.x, ph[0], pl[0]);
            tf32_split(v.y, ph[1], pl[1]);
            tf32_split(v.z, ph[2], pl[2]);
            tf32_split(v.w, ph[3], pl[3]);
        }
        __syncthreads();

        #pragma unroll
        for (int ks = 0; ks < KC2; ks += 8) {
            uint32_t ah[2][4], al[2][4];
            #pragma unroll
            for (int mt = 0; mt < 2; mt++) {
                int mb = m0w + mt * 16;
                int r0 = (mb + g) * XSTR + ks + tig;
                int r1 = (mb + g + 8) * XSTR + ks + tig;
                ah[mt][0] = __float_as_uint(Xh[r0]);
                ah[mt][1] = __float_as_uint(Xh[r1]);
                ah[mt][2] = __float_as_uint(Xh[r0 + 4]);
                ah[mt][3] = __float_as_uint(Xh[r1 + 4]);
                al[mt][0] = __float_as_uint(Xl[r0]);
                al[mt][1] = __float_as_uint(Xl[r1]);
                al[mt][2] = __float_as_uint(Xl[r0 + 4]);
                al[mt][3] = __float_as_uint(Xl[r1 + 4]);
            }
            uint32_t bh[4][2], bl[4][2];
            #pragma unroll
            for (int nt = 0; nt < 4; nt++) {
                int n = n0w + nt * 8 + g;
                int k0 = (ks + tig) * WSTR + n;
                int k1 = (ks + tig + 4) * WSTR + n;
                bh[nt][0] = __float_as_uint(Wh[k0]);
                bh[nt][1] = __float_as_uint(Wh[k1]);
                bl[nt][0] = __float_as_uint(Wl[k0]);
                bl[nt][1] = __float_as_uint(Wl[k1]);
            }
            #pragma unroll
            for (int mt = 0; mt < 2; mt++)
                #pragma unroll
                for (int nt = 0; nt < 4; nt++) {
                    mma_tf32(acc[mt][nt], ah[mt], bh[nt]);  // hi*hi
                    mma_tf32(acc[mt][nt], ah[mt], bl[nt]);  // hi*lo
                    mma_tf32(acc[mt][nt], al[mt], bh[nt]);  // lo*hi
                }
        }
    }

    // epilogue: hout[row] = dis[row] * acc
    #pragma unroll
    for (int mt = 0; mt < 2; mt++) {
        int ra = row0 + m0w + mt * 16 + g;
        int rb = ra + 8;
        float da = (ra < NN) ? g_dis[ra] : 0.f;
        float db = (rb < NN) ? g_dis[rb] : 0.f;
        #pragma unroll
        for (int nt = 0; nt < 4; nt++) {
            int col = n0w + nt * 8 + tig * 2;
            if (ra < NN) {
                float2 o = make_float2(acc[mt][nt][0] * da, acc[mt][nt][1] * da);
                *(float2*)(hout + (size_t)ra * CH + col) = o;
            }
            if (rb < NN) {
                float2 o = make_float2(acc[mt][nt][2] * db, acc[mt][nt][3] * db);
                *(float2*)(hout + (size_t)rb * CH + col) = o;
            }
        }
    }
}

__global__ __launch_bounds__(256) void k_gemm1(const float* __restrict__ x,
                                               const float* __restrict__ W) {
    gemm_tc<CIN, 1>(x, W, g_h1);
}
__global__ __launch_bounds__(256) void k_gemm2(const float* __restrict__ W) {
    gemm_tc<CH, 2>(g_acc1, W, g_h2);
}

// ---------------- CSR gather: dst[i] = dis[i]*(hs[i] + sum_e hs[src_e]) + b ----------------
template <int L>
__global__ __launch_bounds__(256) void k_gather(const float* __restrict__ b,
                                                float* __restrict__ out_arg) {
    const int node = blockIdx.x * 8 + (threadIdx.x >> 5);
    const int lane = threadIdx.x & 31;
    if (node >= NN) return;
    const float* __restrict__ hs = (L == 1) ? g_h1 : g_h2;
    float* __restrict__ dst = (L == 1) ? g_acc1 : out_arg;

    float2 acc = __ldg((const float2*)(hs + (size_t)node * CH) + lane);  // self term

    int e = g_off[node];
    const int s1 = g_end[node];
    for (; e + 4 <= s1; e += 4) {
        int sj0 = __ldg(g_eidx + e);
        int sj1 = __ldg(g_eidx + e + 1);
        int sj2 = __ldg(g_eidx + e + 2);
        int sj3 = __ldg(g_eidx + e + 3);
        float2 v0 = __ldg((const float2*)(hs + (size_t)sj0 * CH) + lane);
        float2 v1 = __ldg((const float2*)(hs + (size_t)sj1 * CH) + lane);
        float2 v2 = __ldg((const float2*)(hs + (size_t)sj2 * CH) + lane);
        float2 v3 = __ldg((const float2*)(hs + (size_t)sj3 * CH) + lane);
        acc.x += v0.x + v1.x + v2.x + v3.x;
        acc.y += v0.y + v1.y + v2.y + v3.y;
    }
    for (; e < s1; e++) {
        int sj = __ldg(g_eidx + e);
        float2 v = __ldg((const float2*)(hs + (size_t)sj * CH) + lane);
        acc.x += v.x;
        acc.y += v.y;
    }

    float ds = g_dis[node];
    float2 bv = __ldg((const float2*)b + lane);
    float2 o;
    o.x = ds * acc.x + bv.x;
    o.y = ds * acc.y + bv.y;
    *((float2*)(dst + (size_t)node * CH) + lane) = o;
}

// ---------------- launch ----------------
extern "C" void kernel_launch(void* const* d_in, const int* in_sizes, int n_in,
                              void* d_out, int out_size) {
    const float* x  = (const float*)d_in[0];
    const void*  ei = d_in[1];
    const float* W1 = (const float*)d_in[2];
    const float* b1 = (const float*)d_in[3];
    const float* W2 = (const float*)d_in[4];
    const float* b2 = (const float*)d_in[5];
    float* out = (float*)d_out;

    k_deg<<<GB_E4, 256>>>(ei);
    k_off<<<NB, 256>>>();
    k_reorder<<<GB_E4, 256>>>(ei);
    k_gemm1<<<(NN + 127) / 128, 256>>>(x, W1);
    k_gather<1><<<(NN + 7) / 8, 256>>>(b1, nullptr);
    k_gemm2<<<(NN + 127) / 128, 256>>>(W2);
    k_gather<2><<<(NN + 7) / 8, 256>>>(b2, out);
}